// round 6
// baseline (speedup 1.0000x reference)
#include <cuda_runtime.h>
#include <cuda_bf16.h>
#include <cstdint>

// out = relu(x @ W_w^T + W_b)   (attention collapses: softmax rows sum to 1).
//
// R6: L1-traffic reduction (R5 was LDSM-bound, L1=75% vs tensor=46%):
//  - warp tile 64x32 (4 warps/CTA) -> 128 B/MMA ldmatrix instead of 170
//  - B (W slice, 64x256) preloaded hi/lo to smem ONCE: no B LDG/STS/convert
//    in the mainloop; B row stride 528 B (mod 128 = 16 -> conflict-free ldsm)
//  - A keeps the R5 double-buffered pipeline, 1 barrier/chunk.

#define D_DIM 256
#define BM 128
#define BN 64
#define BK 32
#define N_CHUNKS (D_DIM / BK)          // 8
#define ROWB_A 80                      // A smem row stride (32+8 bf16)
#define ROWB_B 528                     // B smem row stride (256+8 bf16)

#define AH_BYTES (BM * ROWB_A)         // 10240
#define STAGE_A (2 * AH_BYTES)         // 20480 (hi+lo)
#define OFF_BH (2 * STAGE_A)           // 40960
#define BH_BYTES (BN * ROWB_B)         // 33792
#define OFF_BL (OFF_BH + BH_BYTES)     // 74752
#define SMEM_TOTAL (OFF_BL + BH_BYTES) // 108544

__device__ __forceinline__ uint32_t smem_u32(const void* p) {
    uint32_t a;
    asm("{ .reg .u64 t; cvta.to.shared.u64 t, %1; cvt.u32.u64 %0, t; }" : "=r"(a) : "l"(p));
    return a;
}

__device__ __forceinline__ void ldsm_x4(uint32_t* r, uint32_t addr) {
    asm volatile("ldmatrix.sync.aligned.m8n8.x4.shared.b16 {%0,%1,%2,%3}, [%4];"
                 : "=r"(r[0]), "=r"(r[1]), "=r"(r[2]), "=r"(r[3]) : "r"(addr));
}

__device__ __forceinline__ void mma_bf16(float* d, const uint32_t* a, const uint32_t* b) {
    asm volatile("mma.sync.aligned.m16n8k16.row.col.f32.bf16.bf16.f32 "
                 "{%0,%1,%2,%3}, {%4,%5,%6,%7}, {%8,%9}, {%0,%1,%2,%3};"
                 : "+f"(d[0]), "+f"(d[1]), "+f"(d[2]), "+f"(d[3])
                 : "r"(a[0]), "r"(a[1]), "r"(a[2]), "r"(a[3]),
                   "r"(b[0]), "r"(b[1]));
}

// Split a float4 into bf16 hi + bf16 residual lo, store 8 B each.
__device__ __forceinline__ void split_store(uint32_t hi_addr, uint32_t lo_addr, float4 v) {
    __nv_bfloat162 h0 = __floats2bfloat162_rn(v.x, v.y);
    __nv_bfloat162 h1 = __floats2bfloat162_rn(v.z, v.w);
    float2 f0 = __bfloat1622float2(h0);
    float2 f1 = __bfloat1622float2(h1);
    __nv_bfloat162 l0 = __floats2bfloat162_rn(v.x - f0.x, v.y - f0.y);
    __nv_bfloat162 l1 = __floats2bfloat162_rn(v.z - f1.x, v.w - f1.y);
    uint32_t h0u = *(uint32_t*)&h0, h1u = *(uint32_t*)&h1;
    uint32_t l0u = *(uint32_t*)&l0, l1u = *(uint32_t*)&l1;
    asm volatile("st.shared.v2.b32 [%0], {%1, %2};" :: "r"(hi_addr), "r"(h0u), "r"(h1u) : "memory");
    asm volatile("st.shared.v2.b32 [%0], {%1, %2};" :: "r"(lo_addr), "r"(l0u), "r"(l1u) : "memory");
}

__global__ __launch_bounds__(128, 2)
void fcgat_hmma(const float* __restrict__ A,     // x  [32768, 256]
                const float* __restrict__ W,     // W  [256, 256]
                const float* __restrict__ bias,  // [256]
                float* __restrict__ C)           // [32768, 256]
{
    extern __shared__ __align__(16) unsigned char smem[];
    const uint32_t sb = smem_u32(smem);

    const int t   = threadIdx.x;
    const int l   = t & 31;
    const int wid = t >> 5;          // 4 warps
    const int wm  = wid & 1;         // 2 along M
    const int wn  = wid >> 1;        // 2 along N
    const int m0  = wm * 64;
    const int n0  = wn * 32;

    const float* Ag = A + (size_t)blockIdx.y * BM * D_DIM;
    const float* Bg = W + (size_t)blockIdx.x * BN * D_DIM;

    float acc[4][4][4];
    #pragma unroll
    for (int i = 0; i < 4; i++)
        #pragma unroll
        for (int j = 0; j < 4; j++)
            #pragma unroll
            for (int c = 0; c < 4; c++)
                acc[i][j][c] = 0.0f;

    // ldmatrix lane addresses
    const uint32_t a_lane = (uint32_t)((m0 + (l & 15)) * ROWB_A + (l >> 4) * 16);
    const uint32_t b_lane = (uint32_t)((n0 + (l & 7) + ((l >> 4) << 3)) * ROWB_B
                                       + ((l >> 3) & 1) * 16);

    float4 pa[8];

    // ---- prologue ----
    // Issue A chunk-0 loads first (latency overlaps the B preload work below).
    #pragma unroll
    for (int i = 0; i < 8; i++) {
        int idx = t + i * 128;                 // 1024 float4 over 128 rows x 8
        pa[i] = *(const float4*)(Ag + (size_t)(idx >> 3) * D_DIM + (idx & 7) * 4);
    }
    // B preload: 64 rows x 64 float4 = 4096 -> 32/thread; split hi/lo once.
    #pragma unroll
    for (int i = 0; i < 32; i++) {
        int idx = t + i * 128;
        int row = idx >> 6;                    // 0..63
        int c4  = idx & 63;                    // 0..63
        float4 v = *(const float4*)(Bg + (size_t)row * D_DIM + c4 * 4);
        uint32_t so = (uint32_t)(row * ROWB_B + c4 * 8);
        split_store(sb + OFF_BH + so, sb + OFF_BL + so, v);
    }
    // A chunk 0 into stage 0
    #pragma unroll
    for (int i = 0; i < 8; i++) {
        int idx = t + i * 128;
        uint32_t so = (uint32_t)((idx >> 3) * ROWB_A + (idx & 7) * 8);
        split_store(sb + so, sb + AH_BYTES + so, pa[i]);
    }
    __syncthreads();

    uint32_t stage = 0;
    for (int ch = 0; ch < N_CHUNKS; ch++) {
        const bool more = (ch + 1 < N_CHUNKS);
        const int kn = (ch + 1) * BK;

        // (1) prefetch next A chunk
        if (more) {
            #pragma unroll
            for (int i = 0; i < 8; i++) {
                int idx = t + i * 128;
                pa[i] = *(const float4*)(Ag + (size_t)(idx >> 3) * D_DIM + kn + (idx & 7) * 4);
            }
        }

        // (2) compute current chunk
        const uint32_t abase = sb + stage;
        #pragma unroll
        for (int ks = 0; ks < 2; ks++) {
            const uint32_t koA = (uint32_t)(ks * 32);               // 16 bf16 = 32 B
            const uint32_t koB = (uint32_t)(ch * 64 + ks * 32);     // B covers full K

            uint32_t ah[4][4], al[4][4], bh[2][4], bl[2][4];
            #pragma unroll
            for (int i = 0; i < 4; i++) {
                ldsm_x4(ah[i], abase + a_lane + koA + i * 16 * ROWB_A);
                ldsm_x4(al[i], abase + AH_BYTES + a_lane + koA + i * 16 * ROWB_A);
            }
            #pragma unroll
            for (int jp = 0; jp < 2; jp++) {
                ldsm_x4(bh[jp], sb + OFF_BH + b_lane + koB + jp * 16 * ROWB_B);
                ldsm_x4(bl[jp], sb + OFF_BL + b_lane + koB + jp * 16 * ROWB_B);
            }
            #pragma unroll
            for (int i = 0; i < 4; i++)
                #pragma unroll
                for (int j = 0; j < 4; j++) {
                    const uint32_t* bhf = bh[j >> 1] + (j & 1) * 2;
                    const uint32_t* blf = bl[j >> 1] + (j & 1) * 2;
                    mma_bf16(acc[i][j], ah[i], bhf);   // xh * Wh
                    mma_bf16(acc[i][j], ah[i], blf);   // xh * Wl
                    mma_bf16(acc[i][j], al[i], bhf);   // xl * Wh
                }
        }

        // (3) store next A chunk into the other stage
        if (more) {
            const uint32_t nbase = sb + (stage ^ STAGE_A);
            #pragma unroll
            for (int i = 0; i < 8; i++) {
                int idx = t + i * 128;
                uint32_t so = (uint32_t)((idx >> 3) * ROWB_A + (idx & 7) * 8);
                split_store(nbase + so, nbase + AH_BYTES + so, pa[i]);
            }
        }

        __syncthreads();
        stage ^= STAGE_A;
    }

    // ---- epilogue: bias + relu ----
    const int g  = l >> 2;
    const int tc = l & 3;
    #pragma unroll
    for (int i = 0; i < 4; i++) {
        const size_t r0 = (size_t)blockIdx.y * BM + m0 + 16 * i + g;
        const size_t r1 = r0 + 8;
        #pragma unroll
        for (int j = 0; j < 4; j++) {
            const int col = blockIdx.x * BN + n0 + 8 * j + 2 * tc;
            float2 bv = *(const float2*)(bias + col);
            float2 o0, o1;
            o0.x = fmaxf(acc[i][j][0] + bv.x, 0.0f);
            o0.y = fmaxf(acc[i][j][1] + bv.y, 0.0f);
            o1.x = fmaxf(acc[i][j][2] + bv.x, 0.0f);
            o1.y = fmaxf(acc[i][j][3] + bv.y, 0.0f);
            *(float2*)(C + r0 * D_DIM + col) = o0;
            *(float2*)(C + r1 * D_DIM + col) = o1;
        }
    }
}

extern "C" void kernel_launch(void* const* d_in, const int* in_sizes, int n_in,
                              void* d_out, int out_size)
{
    const float* x   = (const float*)d_in[0];
    const float* W_w = (const float*)d_in[1];
    const float* W_b = (const float*)d_in[2];
    float* out = (float*)d_out;

    int M = in_sizes[0] / D_DIM;                  // 32768
    cudaFuncSetAttribute(fcgat_hmma,
                         cudaFuncAttributeMaxDynamicSharedMemorySize, SMEM_TOTAL);
    dim3 grid(D_DIM / BN, M / BM);                // (4, 256) = 1024 CTAs
    fcgat_hmma<<<grid, 128, SMEM_TOTAL>>>(x, W_w, W_b, out);
}